// round 3
// baseline (speedup 1.0000x reference)
#include <cuda_runtime.h>
#include <cmath>
#include <cstdint>

// Problem dims
#define BB    16
#define TSEQ  1000
#define T2    2000
#define FF    512
#define HH    512
#define NOUT  1024   // 2H

typedef unsigned long long u64;

// ---------------- packed fp32x2 helpers (FFMA2 path, sm_103a) ----------------
__device__ __forceinline__ u64 pack2(float x, float y) {
    u64 r;
    asm("mov.b64 %0, {%1, %2};" : "=l"(r)
        : "r"(__float_as_uint(x)), "r"(__float_as_uint(y)));
    return r;
}
__device__ __forceinline__ float2 unpack2(u64 v) {
    unsigned a, b;
    asm("mov.b64 {%0, %1}, %2;" : "=r"(a), "=r"(b) : "l"(v));
    return make_float2(__uint_as_float(a), __uint_as_float(b));
}
__device__ __forceinline__ void fma2(u64& d, u64 a, u64 b) {
    asm("fma.rn.f32x2 %0, %1, %2, %0;" : "+l"(d) : "l"(a), "l"(b));
}

// ---------------- scratch (device globals; no allocations) ----------------
__device__ float g_wzh[(long long)BB * TSEQ * NOUT];  // 65.5 MB (dedup: half of R1)
__device__ float g_h  [(long long)BB * T2 * HH];      // 65.5 MB: full h history
__device__ float g_A2 [(long long)BB * TSEQ * NOUT];  // 65.5 MB: LayerNorm out (GEMM2 A)
__device__ float g_Wc [NOUT * FF];                    // BN-prescaled combined weight
__device__ float g_shift[NOUT];                       // BN-folded shift

// ---------------- prep: fold BN into weight scale + shift ----------------
__global__ void prep_kernel(const float* __restrict__ Wz, const float* __restrict__ bz,
                            const float* __restrict__ Wh, const float* __restrict__ bh,
                            const float* __restrict__ zg, const float* __restrict__ zb,
                            const float* __restrict__ zm, const float* __restrict__ zv,
                            const float* __restrict__ hg, const float* __restrict__ hb,
                            const float* __restrict__ hm, const float* __restrict__ hv) {
    int n = blockIdx.x;                 // 0..1023
    bool isz = n < HH;
    int r = isz ? n : n - HH;
    float g    = isz ? zg[r] : hg[r];
    float beta = isz ? zb[r] : hb[r];
    float mean = isz ? zm[r] : hm[r];
    float var  = isz ? zv[r] : hv[r];
    float bias = isz ? bz[r] : bh[r];
    float s = g * rsqrtf(var + 1e-5f);
    const float* src = (isz ? Wz : Wh) + (long long)r * FF;
    for (int k = threadIdx.x; k < FF; k += blockDim.x)
        g_Wc[(long long)n * FF + k] = src[k] * s;
    if (threadIdx.x == 0) g_shift[n] = (bias - mean) * s + beta;
}

// ---------------- GEMM1: wzh = x @ Wc^T + shift ----------------
// M=16000 (dedup), N=1024, K=512. 128x128 tile, BK=16, 256 threads, 8x8/thread, FFMA2.
__global__ void __launch_bounds__(256) gemm1_kernel(const float* __restrict__ x) {
    __shared__ float As[16][132];
    __shared__ float Bs[16][132];
    const int bm = blockIdx.x, bn = blockIdx.y;
    const int tid = threadIdx.x;
    const int tx = tid & 15, ty = tid >> 4;

    const float* aptr[2]; int ak[2]; int arow[2];
    const float* bptr[2];
#pragma unroll
    for (int l = 0; l < 2; l++) {
        int idx = tid + l * 256;
        int row = idx >> 2;
        int k4  = (idx & 3) << 2;
        aptr[l] = x + (long long)(bm * 128 + row) * FF + k4;
        ak[l] = k4; arow[l] = row;
        bptr[l] = g_Wc + (long long)(bn * 128 + row) * FF + k4;
    }

    u64 acc[8][4];
#pragma unroll
    for (int i = 0; i < 8; i++)
#pragma unroll
        for (int p = 0; p < 4; p++) acc[i][p] = 0ull;

    for (int kt = 0; kt < FF; kt += 16) {
#pragma unroll
        for (int l = 0; l < 2; l++) {
            float4 v = *(const float4*)(aptr[l] + kt);
            As[ak[l] + 0][arow[l]] = v.x; As[ak[l] + 1][arow[l]] = v.y;
            As[ak[l] + 2][arow[l]] = v.z; As[ak[l] + 3][arow[l]] = v.w;
            float4 w = *(const float4*)(bptr[l] + kt);
            Bs[ak[l] + 0][arow[l]] = w.x; Bs[ak[l] + 1][arow[l]] = w.y;
            Bs[ak[l] + 2][arow[l]] = w.z; Bs[ak[l] + 3][arow[l]] = w.w;
        }
        __syncthreads();
#pragma unroll
        for (int kk = 0; kk < 16; kk++) {
            float a[8];
            *(float4*)a       = *(const float4*)&As[kk][ty * 8];
            *(float4*)(a + 4) = *(const float4*)&As[kk][ty * 8 + 4];
            const u64* bp = (const u64*)&Bs[kk][tx * 8];   // 4 packed col-pairs
            u64 b0 = bp[0], b1 = bp[1], b2 = bp[2], b3 = bp[3];
#pragma unroll
            for (int i = 0; i < 8; i++) {
                u64 ap = pack2(a[i], a[i]);
                fma2(acc[i][0], ap, b0);
                fma2(acc[i][1], ap, b1);
                fma2(acc[i][2], ap, b2);
                fma2(acc[i][3], ap, b3);
            }
        }
        __syncthreads();
    }
    int n0 = bn * 128 + tx * 8;
    float4 s0 = *(const float4*)(g_shift + n0);
    float4 s1 = *(const float4*)(g_shift + n0 + 4);
#pragma unroll
    for (int i = 0; i < 8; i++) {
        int m = bm * 128 + ty * 8 + i;
        float* cp = g_wzh + (long long)m * NOUT + n0;
        float2 c0 = unpack2(acc[i][0]), c1 = unpack2(acc[i][1]);
        float2 c2 = unpack2(acc[i][2]), c3 = unpack2(acc[i][3]);
        float4 o0 = {c0.x + s0.x, c0.y + s0.y, c1.x + s0.z, c1.y + s0.w};
        float4 o1 = {c2.x + s1.x, c2.y + s1.y, c3.x + s1.z, c3.y + s1.w};
        *(float4*)cp = o0; *(float4*)(cp + 4) = o1;
    }
}

// ---------------- Recurrence: one 8-CTA cluster per batch ----------------
// Per CTA: 64 j-indices -> 128 dots (uz,uh). Thread t: dot d=t>>1, k-half=t&1.
// U split: first 128 k of each thread slice in regs (packed pairs), last 128 k in smem.
#define NR   8
#define JPC  64
#define SMEM_BYTES (4096 + 32 * 256 * 16)   // h ping-pong + Usm2 ulonglong2[32][256]

__global__ void __cluster_dims__(NR, 1, 1) __launch_bounds__(256, 1)
recur_kernel(const float* __restrict__ U) {
    extern __shared__ float smem[];
    float*      hbuf = smem;                          // [2][512]
    ulonglong2* Usm  = (ulonglong2*)(smem + 1024);    // [32][256]

    const int rank = blockIdx.x;               // cluster rank 0..7
    const int b    = blockIdx.y;               // batch
    const int tid  = threadIdx.x;
    const int d    = tid >> 1;                 // dot id 0..127
    const int half = tid & 1;                  // k half
    const int jj   = d >> 1;
    const int type = d & 1;                    // 0: z-gate, 1: h-cand
    const int j    = rank * JPC + jj;
    const int grow = type ? (HH + j) : j;      // U row
    const int koff = half * 256;

    // U slice: 128 k as 64 packed f32x2 pairs in registers
    u64 Ur[64];
    {
        const ulonglong2* up = (const ulonglong2*)(U + (long long)grow * HH + koff);
#pragma unroll
        for (int i = 0; i < 32; i++) { ulonglong2 v = up[i]; Ur[2*i] = v.x; Ur[2*i+1] = v.y; }
        // next 128 k to smem, [i][tid] layout
        const ulonglong2* up2 = (const ulonglong2*)(U + (long long)grow * HH + koff + 128);
        for (int i = 0; i < 32; i++) Usm[i * 256 + tid] = up2[i];
    }

    // h[0] = 0
    for (int i = tid; i < 1024; i += 256) hbuf[i] = 0.f;

    asm volatile("barrier.cluster.arrive.aligned;" ::: "memory");
    asm volatile("barrier.cluster.wait.aligned;"   ::: "memory");

    const bool owner = (tid & 3) == 0;
    const int  jown  = tid >> 2;               // 0..63
    const int  jg    = rank * JPC + jown;      // global h index this lane updates
    float* hout = g_h + (long long)b * T2 * HH + jg;

    // wzh row for step t (dedup: second half reads mirrored batch's rows)
    auto rowp = [&](int t) -> const float* {
        int r = (t < TSEQ) ? (b * TSEQ + t) : ((BB - 1 - b) * TSEQ + (t - TSEQ));
        return g_wzh + (long long)r * NOUT + jg;
    };

    float pz = 0.f, ph = 0.f;
    if (owner) { const float* rp = rowp(0); pz = rp[0]; ph = rp[HH]; }

    for (int t = 0; t < T2; t++) {
        const float* hc = hbuf + (t & 1) * 512;
        float*       hn = hbuf + ((t + 1) & 1) * 512;

        // prefetch next step's wz/wh
        float pz2 = 0.f, ph2 = 0.f;
        if (owner && t + 1 < T2) { const float* rp = rowp(t + 1); pz2 = rp[0]; ph2 = rp[HH]; }

        u64 a0 = 0ull, a1 = 0ull, a2 = 0ull, a3 = 0ull;
        // register-resident U half (128 k): 32 x LDS.128 (broadcast) + 64 FFMA2
        const ulonglong2* h4 = (const ulonglong2*)(hc + koff);
#pragma unroll
        for (int i = 0; i < 32; i += 2) {
            ulonglong2 hv0 = h4[i];
            fma2(a0, Ur[2*i],   hv0.x);
            fma2(a1, Ur[2*i+1], hv0.y);
            ulonglong2 hv1 = h4[i + 1];
            fma2(a2, Ur[2*i+2], hv1.x);
            fma2(a3, Ur[2*i+3], hv1.y);
        }
        // smem U half (128 k): 32 x (LDS.128 U + LDS.128 h) + 64 FFMA2
        const ulonglong2* h2 = (const ulonglong2*)(hc + koff + 128);
#pragma unroll
        for (int i = 0; i < 32; i++) {
            ulonglong2 uv = Usm[i * 256 + tid];
            ulonglong2 hv = h2[i];
            fma2((i & 1) ? a2 : a0, uv.x, hv.x);
            fma2((i & 1) ? a3 : a1, uv.y, hv.y);
        }
        float2 f0 = unpack2(a0), f1 = unpack2(a1), f2 = unpack2(a2), f3 = unpack2(a3);
        float acc = ((f0.x + f0.y) + (f1.x + f1.y)) + ((f2.x + f2.y) + (f3.x + f3.y));

        // reduce 2 k-halves; then exchange z<->h dot
        acc += __shfl_xor_sync(0xffffffffu, acc, 1);
        float other = __shfl_xor_sync(0xffffffffu, acc, 2);

        if (owner) {
            float uz = acc, uh = other;
            float zt = 1.f / (1.f + expf(-(pz + uz)));
            float hcand = fmaxf(ph + uh, 0.f);
            float hold = hc[jg];
            float hnew = zt * hold + (1.f - zt) * hcand;
            hout[(long long)t * HH] = hnew;
            uint32_t laddr = (uint32_t)__cvta_generic_to_shared(hn + jg);
#pragma unroll
            for (int rr = 0; rr < NR; rr++) {
                uint32_t ra;
                asm("mapa.shared::cluster.u32 %0, %1, %2;" : "=r"(ra) : "r"(laddr), "r"(rr));
                asm volatile("st.shared::cluster.f32 [%0], %1;" :: "r"(ra), "f"(hnew) : "memory");
            }
        }
        pz = pz2; ph = ph2;
        asm volatile("barrier.cluster.arrive.aligned;" ::: "memory");  // release: orders DSMEM stores
        asm volatile("barrier.cluster.wait.aligned;"   ::: "memory");  // acquire
    }
}

// ---------------- LayerNorm over concat(h_f, h_b_rev) ----------------
__global__ void __launch_bounds__(256) ln_kernel(const float* __restrict__ lng,
                                                 const float* __restrict__ lnb) {
    int m = blockIdx.x;                 // 0..15999
    int b = m / TSEQ, t = m - b * TSEQ;
    int tid = threadIdx.x;
    int d0 = tid * 4;
    const float* src = (d0 < HH)
        ? (g_h + (long long)(b * T2 + t) * HH + d0)
        : (g_h + (long long)((BB - 1 - b) * T2 + TSEQ + t) * HH + (d0 - HH));
    float4 v = *(const float4*)src;
    float s = v.x + v.y + v.z + v.w;
    float q = v.x*v.x + v.y*v.y + v.z*v.z + v.w*v.w;
#pragma unroll
    for (int o = 16; o; o >>= 1) {
        s += __shfl_xor_sync(0xffffffffu, s, o);
        q += __shfl_xor_sync(0xffffffffu, q, o);
    }
    __shared__ float ss[8], qq[8];
    __shared__ float mu_s, rs_s;
    if ((tid & 31) == 0) { ss[tid >> 5] = s; qq[tid >> 5] = q; }
    __syncthreads();
    if (tid == 0) {
        float S = 0.f, Q = 0.f;
#pragma unroll
        for (int i = 0; i < 8; i++) { S += ss[i]; Q += qq[i]; }
        float mu = S * (1.f / NOUT);
        float var = Q * (1.f / NOUT) - mu * mu;
        mu_s = mu; rs_s = rsqrtf(var + 1e-5f);
    }
    __syncthreads();
    float mu = mu_s, rs = rs_s;
    float4 g4 = *(const float4*)(lng + d0);
    float4 b4 = *(const float4*)(lnb + d0);
    float4 o;
    o.x = (v.x - mu) * rs * g4.x + b4.x;
    o.y = (v.y - mu) * rs * g4.y + b4.y;
    o.z = (v.z - mu) * rs * g4.z + b4.z;
    o.w = (v.w - mu) * rs * g4.w + b4.w;
    *(float4*)(g_A2 + (long long)m * NOUT + d0) = o;
}

// ---------------- GEMM2: tanh(A2 @ pj_W^T + pj_b) -> d_out ----------------
__global__ void __launch_bounds__(256) gemm2_kernel(const float* __restrict__ pjW,
                                                    const float* __restrict__ pjb,
                                                    float* __restrict__ out) {
    __shared__ float As[16][132];
    __shared__ float Bs[16][132];
    const int bm = blockIdx.x, bn = blockIdx.y;
    const int tid = threadIdx.x;
    const int tx = tid & 15, ty = tid >> 4;

    const float* aptr[2]; int ak[2]; int arow[2];
    const float* bptr[2];
#pragma unroll
    for (int l = 0; l < 2; l++) {
        int idx = tid + l * 256;
        int row = idx >> 2;
        int k4  = (idx & 3) << 2;
        aptr[l] = g_A2 + (long long)(bm * 128 + row) * NOUT + k4;
        ak[l] = k4; arow[l] = row;
        bptr[l] = pjW + (long long)(bn * 128 + row) * NOUT + k4;
    }

    u64 acc[8][4];
#pragma unroll
    for (int i = 0; i < 8; i++)
#pragma unroll
        for (int p = 0; p < 4; p++) acc[i][p] = 0ull;

    for (int kt = 0; kt < NOUT; kt += 16) {
#pragma unroll
        for (int l = 0; l < 2; l++) {
            float4 v = *(const float4*)(aptr[l] + kt);
            As[ak[l] + 0][arow[l]] = v.x; As[ak[l] + 1][arow[l]] = v.y;
            As[ak[l] + 2][arow[l]] = v.z; As[ak[l] + 3][arow[l]] = v.w;
            float4 w = *(const float4*)(bptr[l] + kt);
            Bs[ak[l] + 0][arow[l]] = w.x; Bs[ak[l] + 1][arow[l]] = w.y;
            Bs[ak[l] + 2][arow[l]] = w.z; Bs[ak[l] + 3][arow[l]] = w.w;
        }
        __syncthreads();
#pragma unroll
        for (int kk = 0; kk < 16; kk++) {
            float a[8];
            *(float4*)a       = *(const float4*)&As[kk][ty * 8];
            *(float4*)(a + 4) = *(const float4*)&As[kk][ty * 8 + 4];
            const u64* bp = (const u64*)&Bs[kk][tx * 8];
            u64 b0 = bp[0], b1 = bp[1], b2 = bp[2], b3 = bp[3];
#pragma unroll
            for (int i = 0; i < 8; i++) {
                u64 ap = pack2(a[i], a[i]);
                fma2(acc[i][0], ap, b0);
                fma2(acc[i][1], ap, b1);
                fma2(acc[i][2], ap, b2);
                fma2(acc[i][3], ap, b3);
            }
        }
        __syncthreads();
    }
    int n0 = bn * 128 + tx * 8;
    float4 s0 = *(const float4*)(pjb + n0);
    float4 s1 = *(const float4*)(pjb + n0 + 4);
#pragma unroll
    for (int i = 0; i < 8; i++) {
        int m = bm * 128 + ty * 8 + i;
        float* cp = out + (long long)m * NOUT + n0;
        float2 c0 = unpack2(acc[i][0]), c1 = unpack2(acc[i][1]);
        float2 c2 = unpack2(acc[i][2]), c3 = unpack2(acc[i][3]);
        float4 o0 = {tanhf(c0.x + s0.x), tanhf(c0.y + s0.y),
                     tanhf(c1.x + s0.z), tanhf(c1.y + s0.w)};
        float4 o1 = {tanhf(c2.x + s1.x), tanhf(c2.y + s1.y),
                     tanhf(c3.x + s1.z), tanhf(c3.y + s1.w)};
        *(float4*)cp = o0; *(float4*)(cp + 4) = o1;
    }
}

// ---------------- tail: x_len passthrough (value-cast to float) ----------------
__global__ void tail_kernel(const int* __restrict__ xlen, float* __restrict__ out, int extra) {
    int i = threadIdx.x;
    if (i < 16 && i < extra) out[(long long)BB * TSEQ * NOUT + i] = (float)xlen[i];
}

// ---------------- launch ----------------
extern "C" void kernel_launch(void* const* d_in, const int* in_sizes, int n_in,
                              void* d_out, int out_size) {
    const float* x   = (const float*)d_in[0];
    const int*  xlen = (const int*)  d_in[1];
    const float* Wz  = (const float*)d_in[2];
    const float* bz  = (const float*)d_in[3];
    const float* Wh  = (const float*)d_in[4];
    const float* bh  = (const float*)d_in[5];
    const float* U   = (const float*)d_in[6];
    const float* zg  = (const float*)d_in[7];
    const float* zb  = (const float*)d_in[8];
    const float* zm  = (const float*)d_in[9];
    const float* zv  = (const float*)d_in[10];
    const float* hg  = (const float*)d_in[11];
    const float* hb  = (const float*)d_in[12];
    const float* hm  = (const float*)d_in[13];
    const float* hv  = (const float*)d_in[14];
    const float* lng = (const float*)d_in[15];
    const float* lnb = (const float*)d_in[16];
    const float* pjW = (const float*)d_in[17];
    const float* pjb = (const float*)d_in[18];
    float* out = (float*)d_out;

    prep_kernel<<<NOUT, 128>>>(Wz, bz, Wh, bh, zg, zb, zm, zv, hg, hb, hm, hv);
    gemm1_kernel<<<dim3(125, 8), 256>>>(x);    // M=16000 (dedup)

    cudaFuncSetAttribute(recur_kernel, cudaFuncAttributeMaxDynamicSharedMemorySize, SMEM_BYTES);
    recur_kernel<<<dim3(NR, BB), 256, SMEM_BYTES>>>(U);

    ln_kernel<<<BB * TSEQ, 256>>>(lng, lnb);
    gemm2_kernel<<<dim3(125, 8), 256>>>(pjW, pjb, out);

    long long total = (long long)BB * TSEQ * NOUT;
    if ((long long)out_size > total)
        tail_kernel<<<1, 32>>>(xlen, out, (int)((long long)out_size - total));
}

// round 5
// speedup vs baseline: 1.5985x; 1.5985x over previous
#include <cuda_runtime.h>
#include <cmath>
#include <cstdint>

// Problem dims
#define BB    16
#define TSEQ  1000
#define T2    2000
#define FF    512
#define HH    512
#define NOUT  1024   // 2H

// ---------------- scratch (device globals; no allocations) ----------------
__device__ float g_wzh[(long long)BB * TSEQ * NOUT];  // 65.5 MB (dedup)
__device__ float g_h  [(long long)BB * T2 * HH];      // 65.5 MB: full h history
__device__ float g_A2 [(long long)BB * TSEQ * NOUT];  // 65.5 MB: LayerNorm out (GEMM2 A)
__device__ float g_Wc [NOUT * FF];                    // BN-prescaled combined weight
__device__ float g_shift[NOUT];                       // BN-folded shift

// ---------------- prep: fold BN into weight scale + shift ----------------
__global__ void prep_kernel(const float* __restrict__ Wz, const float* __restrict__ bz,
                            const float* __restrict__ Wh, const float* __restrict__ bh,
                            const float* __restrict__ zg, const float* __restrict__ zb,
                            const float* __restrict__ zm, const float* __restrict__ zv,
                            const float* __restrict__ hg, const float* __restrict__ hb,
                            const float* __restrict__ hm, const float* __restrict__ hv) {
    int n = blockIdx.x;                 // 0..1023
    bool isz = n < HH;
    int r = isz ? n : n - HH;
    float g    = isz ? zg[r] : hg[r];
    float beta = isz ? zb[r] : hb[r];
    float mean = isz ? zm[r] : hm[r];
    float var  = isz ? zv[r] : hv[r];
    float bias = isz ? bz[r] : bh[r];
    float s = g * rsqrtf(var + 1e-5f);
    const float* src = (isz ? Wz : Wh) + (long long)r * FF;
    for (int k = threadIdx.x; k < FF; k += blockDim.x)
        g_Wc[(long long)n * FF + k] = src[k] * s;
    if (threadIdx.x == 0) g_shift[n] = (bias - mean) * s + beta;
}

// ---------------- GEMM1: wzh = x @ Wc^T + shift ----------------
// M=16000 (dedup), N=1024, K=512. 128x128 tile, BK=16, 256 threads, 8x8/thread.
__global__ void __launch_bounds__(256) gemm1_kernel(const float* __restrict__ x) {
    __shared__ float As[16][132];
    __shared__ float Bs[16][132];
    const int bm = blockIdx.x, bn = blockIdx.y;
    const int tid = threadIdx.x;
    const int tx = tid & 15, ty = tid >> 4;

    const float* aptr[2]; int ak[2]; int arow[2];
    const float* bptr[2];
#pragma unroll
    for (int l = 0; l < 2; l++) {
        int idx = tid + l * 256;
        int row = idx >> 2;
        int k4  = (idx & 3) << 2;
        aptr[l] = x + (long long)(bm * 128 + row) * FF + k4;
        ak[l] = k4; arow[l] = row;
        bptr[l] = g_Wc + (long long)(bn * 128 + row) * FF + k4;
    }

    float acc[8][8] = {};
    for (int kt = 0; kt < FF; kt += 16) {
#pragma unroll
        for (int l = 0; l < 2; l++) {
            float4 v = *(const float4*)(aptr[l] + kt);
            As[ak[l] + 0][arow[l]] = v.x; As[ak[l] + 1][arow[l]] = v.y;
            As[ak[l] + 2][arow[l]] = v.z; As[ak[l] + 3][arow[l]] = v.w;
            float4 w = *(const float4*)(bptr[l] + kt);
            Bs[ak[l] + 0][arow[l]] = w.x; Bs[ak[l] + 1][arow[l]] = w.y;
            Bs[ak[l] + 2][arow[l]] = w.z; Bs[ak[l] + 3][arow[l]] = w.w;
        }
        __syncthreads();
#pragma unroll
        for (int kk = 0; kk < 16; kk++) {
            float a[8], bb[8];
            *(float4*)a       = *(const float4*)&As[kk][ty * 8];
            *(float4*)(a + 4) = *(const float4*)&As[kk][ty * 8 + 4];
            *(float4*)bb       = *(const float4*)&Bs[kk][tx * 8];
            *(float4*)(bb + 4) = *(const float4*)&Bs[kk][tx * 8 + 4];
#pragma unroll
            for (int i = 0; i < 8; i++)
#pragma unroll
                for (int j = 0; j < 8; j++) acc[i][j] += a[i] * bb[j];
        }
        __syncthreads();
    }
    int n0 = bn * 128 + tx * 8;
    float4 s0 = *(const float4*)(g_shift + n0);
    float4 s1 = *(const float4*)(g_shift + n0 + 4);
#pragma unroll
    for (int i = 0; i < 8; i++) {
        int m = bm * 128 + ty * 8 + i;
        float* cp = g_wzh + (long long)m * NOUT + n0;
        float4 o0 = {acc[i][0] + s0.x, acc[i][1] + s0.y, acc[i][2] + s0.z, acc[i][3] + s0.w};
        float4 o1 = {acc[i][4] + s1.x, acc[i][5] + s1.y, acc[i][6] + s1.z, acc[i][7] + s1.w};
        *(float4*)cp = o0; *(float4*)(cp + 4) = o1;
    }
}

// ---------------- dummy: shifts ncu capture slot onto recur_kernel ----------------
__global__ void dummy_kernel() {}

// ---------------- Recurrence: one 8-CTA cluster per batch ----------------
// Per CTA: 64 j-indices -> 128 dots (uz,uh). Thread t: dot d=t>>1, k-half=t&1.
// U split: first 128 k of each thread slice in registers, last 128 k in smem.
#define NR   8
#define JPC  64
#define SMEM_BYTES (4096 + 64 * 256 * 8)   // h ping-pong (2*512 f32) + U smem (float2[64][256])

__global__ void __cluster_dims__(NR, 1, 1) __launch_bounds__(256, 1)
recur_kernel(const float* __restrict__ U) {
    extern __shared__ float smem[];
    float*  hbuf = smem;                       // [2][512]
    float2* Usm  = (float2*)(smem + 1024);     // [64][256]

    const int rank = blockIdx.x;               // cluster rank 0..7
    const int b    = blockIdx.y;               // batch
    const int tid  = threadIdx.x;
    const int d    = tid >> 1;                 // dot id 0..127
    const int half = tid & 1;                  // k half
    const int jj   = d >> 1;
    const int type = d & 1;                    // 0: z-gate, 1: h-cand
    const int j    = rank * JPC + jj;
    const int grow = type ? (HH + j) : j;      // U row
    const int koff = half * 256;

    // Load U slice: 128 k in registers
    float Ur[128];
    const float4* up = (const float4*)(U + (long long)grow * HH + koff);
#pragma unroll
    for (int i = 0; i < 32; i++) {
        float4 v = up[i];
        Ur[4*i] = v.x; Ur[4*i+1] = v.y; Ur[4*i+2] = v.z; Ur[4*i+3] = v.w;
    }
    // 128 k in smem, k-major layout [i2][tid] to avoid bank conflicts
    const float2* up2 = (const float2*)(U + (long long)grow * HH + koff + 128);
    for (int i = 0; i < 64; i++) Usm[i * 256 + tid] = up2[i];

    // h[0] = 0
    for (int i = tid; i < 1024; i += 256) hbuf[i] = 0.f;

    asm volatile("barrier.cluster.arrive.aligned;" ::: "memory");
    asm volatile("barrier.cluster.wait.aligned;"   ::: "memory");

    const bool owner = (tid & 3) == 0;
    const int  jown  = tid >> 2;               // 0..63
    const int  jg    = rank * JPC + jown;      // global h index this lane updates
    float* hout = g_h + (long long)b * T2 * HH + jg;

    // wzh row for step t (dedup: second half reads mirrored batch's rows)
    auto rowp = [&](int t) -> const float* {
        int r = (t < TSEQ) ? (b * TSEQ + t) : ((BB - 1 - b) * TSEQ + (t - TSEQ));
        return g_wzh + (long long)r * NOUT + jg;
    };

    float pz = 0.f, ph = 0.f;
    if (owner) { const float* rp = rowp(0); pz = rp[0]; ph = rp[HH]; }

    for (int t = 0; t < T2; t++) {
        const float* hc = hbuf + (t & 1) * 512;
        float*       hn = hbuf + ((t + 1) & 1) * 512;

        // prefetch next step's wz/wh (latency hidden under dot compute)
        float pz2 = 0.f, ph2 = 0.f;
        if (owner && t + 1 < T2) { const float* rp = rowp(t + 1); pz2 = rp[0]; ph2 = rp[HH]; }

        // 4 independent accumulators: break the serial FMA chain (ILP x4)
        float a0 = 0.f, a1 = 0.f, a2 = 0.f, a3 = 0.f;
        const float4* h4 = (const float4*)(hc + koff);
#pragma unroll
        for (int i = 0; i < 32; i++) {
            float4 hv = h4[i];
            a0 += Ur[4*i]   * hv.x;
            a1 += Ur[4*i+1] * hv.y;
            a2 += Ur[4*i+2] * hv.z;
            a3 += Ur[4*i+3] * hv.w;
        }
        const float2* h2 = (const float2*)(hc + koff + 128);
#pragma unroll
        for (int i = 0; i < 64; i++) {
            float2 uv = Usm[i * 256 + tid];
            float2 hv = h2[i];
            if (i & 1) { a2 += uv.x * hv.x; a3 += uv.y * hv.y; }
            else       { a0 += uv.x * hv.x; a1 += uv.y * hv.y; }
        }
        float acc = (a0 + a1) + (a2 + a3);

        // reduce 2 k-halves; then exchange z<->h dot
        acc += __shfl_xor_sync(0xffffffffu, acc, 1);
        float other = __shfl_xor_sync(0xffffffffu, acc, 2);

        if (owner) {
            float uz = acc, uh = other;
            float zt = 1.f / (1.f + expf(-(pz + uz)));
            float hcand = fmaxf(ph + uh, 0.f);
            float hold = hc[jg];
            float hnew = zt * hold + (1.f - zt) * hcand;
            hout[(long long)t * HH] = hnew;
            uint32_t laddr = (uint32_t)__cvta_generic_to_shared(hn + jg);
#pragma unroll
            for (int rr = 0; rr < NR; rr++) {
                uint32_t ra;
                asm("mapa.shared::cluster.u32 %0, %1, %2;" : "=r"(ra) : "r"(laddr), "r"(rr));
                asm volatile("st.shared::cluster.f32 [%0], %1;" :: "r"(ra), "f"(hnew) : "memory");
            }
        }
        pz = pz2; ph = ph2;
        asm volatile("barrier.cluster.arrive.aligned;" ::: "memory");  // release: orders DSMEM stores
        asm volatile("barrier.cluster.wait.aligned;"   ::: "memory");  // acquire
    }
}

// ---------------- LayerNorm over concat(h_f, h_b_rev) ----------------
__global__ void __launch_bounds__(256) ln_kernel(const float* __restrict__ lng,
                                                 const float* __restrict__ lnb) {
    int m = blockIdx.x;                 // 0..15999
    int b = m / TSEQ, t = m - b * TSEQ;
    int tid = threadIdx.x;
    int d0 = tid * 4;
    const float* src = (d0 < HH)
        ? (g_h + (long long)(b * T2 + t) * HH + d0)
        : (g_h + (long long)((BB - 1 - b) * T2 + TSEQ + t) * HH + (d0 - HH));
    float4 v = *(const float4*)src;
    float s = v.x + v.y + v.z + v.w;
    float q = v.x*v.x + v.y*v.y + v.z*v.z + v.w*v.w;
#pragma unroll
    for (int o = 16; o; o >>= 1) {
        s += __shfl_xor_sync(0xffffffffu, s, o);
        q += __shfl_xor_sync(0xffffffffu, q, o);
    }
    __shared__ float ss[8], qq[8];
    __shared__ float mu_s, rs_s;
    if ((tid & 31) == 0) { ss[tid >> 5] = s; qq[tid >> 5] = q; }
    __syncthreads();
    if (tid == 0) {
        float S = 0.f, Q = 0.f;
#pragma unroll
        for (int i = 0; i < 8; i++) { S += ss[i]; Q += qq[i]; }
        float mu = S * (1.f / NOUT);
        float var = Q * (1.f / NOUT) - mu * mu;
        mu_s = mu; rs_s = rsqrtf(var + 1e-5f);
    }
    __syncthreads();
    float mu = mu_s, rs = rs_s;
    float4 g4 = *(const float4*)(lng + d0);
    float4 b4 = *(const float4*)(lnb + d0);
    float4 o;
    o.x = (v.x - mu) * rs * g4.x + b4.x;
    o.y = (v.y - mu) * rs * g4.y + b4.y;
    o.z = (v.z - mu) * rs * g4.z + b4.z;
    o.w = (v.w - mu) * rs * g4.w + b4.w;
    *(float4*)(g_A2 + (long long)m * NOUT + d0) = o;
}

// ---------------- GEMM2: tanh(A2 @ pj_W^T + pj_b) -> d_out ----------------
__global__ void __launch_bounds__(256) gemm2_kernel(const float* __restrict__ pjW,
                                                    const float* __restrict__ pjb,
                                                    float* __restrict__ out) {
    __shared__ float As[16][132];
    __shared__ float Bs[16][132];
    const int bm = blockIdx.x, bn = blockIdx.y;
    const int tid = threadIdx.x;
    const int tx = tid & 15, ty = tid >> 4;

    const float* aptr[2]; int ak[2]; int arow[2];
    const float* bptr[2];
#pragma unroll
    for (int l = 0; l < 2; l++) {
        int idx = tid + l * 256;
        int row = idx >> 2;
        int k4  = (idx & 3) << 2;
        aptr[l] = g_A2 + (long long)(bm * 128 + row) * NOUT + k4;
        ak[l] = k4; arow[l] = row;
        bptr[l] = pjW + (long long)(bn * 128 + row) * NOUT + k4;
    }

    float acc[8][8] = {};
    for (int kt = 0; kt < NOUT; kt += 16) {
#pragma unroll
        for (int l = 0; l < 2; l++) {
            float4 v = *(const float4*)(aptr[l] + kt);
            As[ak[l] + 0][arow[l]] = v.x; As[ak[l] + 1][arow[l]] = v.y;
            As[ak[l] + 2][arow[l]] = v.z; As[ak[l] + 3][arow[l]] = v.w;
            float4 w = *(const float4*)(bptr[l] + kt);
            Bs[ak[l] + 0][arow[l]] = w.x; Bs[ak[l] + 1][arow[l]] = w.y;
            Bs[ak[l] + 2][arow[l]] = w.z; Bs[ak[l] + 3][arow[l]] = w.w;
        }
        __syncthreads();
#pragma unroll
        for (int kk = 0; kk < 16; kk++) {
            float a[8], bb[8];
            *(float4*)a       = *(const float4*)&As[kk][ty * 8];
            *(float4*)(a + 4) = *(const float4*)&As[kk][ty * 8 + 4];
            *(float4*)bb       = *(const float4*)&Bs[kk][tx * 8];
            *(float4*)(bb + 4) = *(const float4*)&Bs[kk][tx * 8 + 4];
#pragma unroll
            for (int i = 0; i < 8; i++)
#pragma unroll
                for (int j = 0; j < 8; j++) acc[i][j] += a[i] * bb[j];
        }
        __syncthreads();
    }
    int n0 = bn * 128 + tx * 8;
    float4 s0 = *(const float4*)(pjb + n0);
    float4 s1 = *(const float4*)(pjb + n0 + 4);
#pragma unroll
    for (int i = 0; i < 8; i++) {
        int m = bm * 128 + ty * 8 + i;
        float* cp = out + (long long)m * NOUT + n0;
        float4 o0 = {tanhf(acc[i][0] + s0.x), tanhf(acc[i][1] + s0.y),
                     tanhf(acc[i][2] + s0.z), tanhf(acc[i][3] + s0.w)};
        float4 o1 = {tanhf(acc[i][4] + s1.x), tanhf(acc[i][5] + s1.y),
                     tanhf(acc[i][6] + s1.z), tanhf(acc[i][7] + s1.w)};
        *(float4*)cp = o0; *(float4*)(cp + 4) = o1;
    }
}

// ---------------- tail: x_len passthrough (value-cast to float) ----------------
__global__ void tail_kernel(const int* __restrict__ xlen, float* __restrict__ out, int extra) {
    int i = threadIdx.x;
    if (i < 16 && i < extra) out[(long long)BB * TSEQ * NOUT + i] = (float)xlen[i];
}

// ---------------- launch ----------------
extern "C" void kernel_launch(void* const* d_in, const int* in_sizes, int n_in,
                              void* d_out, int out_size) {
    const float* x   = (const float*)d_in[0];
    const int*  xlen = (const int*)  d_in[1];
    const float* Wz  = (const float*)d_in[2];
    const float* bz  = (const float*)d_in[3];
    const float* Wh  = (const float*)d_in[4];
    const float* bh  = (const float*)d_in[5];
    const float* U   = (const float*)d_in[6];
    const float* zg  = (const float*)d_in[7];
    const float* zb  = (const float*)d_in[8];
    const float* zm  = (const float*)d_in[9];
    const float* zv  = (const float*)d_in[10];
    const float* hg  = (const float*)d_in[11];
    const float* hb  = (const float*)d_in[12];
    const float* hm  = (const float*)d_in[13];
    const float* hv  = (const float*)d_in[14];
    const float* lng = (const float*)d_in[15];
    const float* lnb = (const float*)d_in[16];
    const float* pjW = (const float*)d_in[17];
    const float* pjb = (const float*)d_in[18];
    float* out = (float*)d_out;

    prep_kernel<<<NOUT, 128>>>(Wz, bz, Wh, bh, zg, zb, zm, zv, hg, hb, hm, hv);
    gemm1_kernel<<<dim3(125, 8), 256>>>(x);    // M=16000 (dedup)

    dummy_kernel<<<1, 32>>>();                 // shift ncu capture slot onto recur

    cudaFuncSetAttribute(recur_kernel, cudaFuncAttributeMaxDynamicSharedMemorySize, SMEM_BYTES);
    recur_kernel<<<dim3(NR, BB), 256, SMEM_BYTES>>>(U);

    ln_kernel<<<BB * TSEQ, 256>>>(lng, lnb);
    gemm2_kernel<<<dim3(125, 8), 256>>>(pjW, pjb, out);

    long long total = (long long)BB * TSEQ * NOUT;
    if ((long long)out_size > total)
        tail_kernel<<<1, 32>>>(xlen, out, (int)((long long)out_size - total));
}

// round 7
// speedup vs baseline: 1.7563x; 1.0987x over previous
#include <cuda_runtime.h>
#include <cmath>
#include <cstdint>

// Problem dims
#define BB    16
#define TSEQ  1000
#define T2    2000
#define FF    512
#define HH    512
#define NOUT  1024   // 2H

// ---------------- scratch (device globals; no allocations) ----------------
__device__ float g_wzh[(long long)BB * TSEQ * NOUT];  // 65.5 MB (dedup)
__device__ float g_h  [(long long)BB * T2 * HH];      // 65.5 MB: full h history
__device__ float g_A2 [(long long)BB * TSEQ * NOUT]; // 65.5 MB: LayerNorm out (GEMM2 A)
__device__ float g_Wc [NOUT * FF];                    // BN-prescaled combined weight
__device__ float g_shift[NOUT];                       // BN-folded shift

// ---------------- prep: fold BN into weight scale + shift ----------------
__global__ void prep_kernel(const float* __restrict__ Wz, const float* __restrict__ bz,
                            const float* __restrict__ Wh, const float* __restrict__ bh,
                            const float* __restrict__ zg, const float* __restrict__ zb,
                            const float* __restrict__ zm, const float* __restrict__ zv,
                            const float* __restrict__ hg, const float* __restrict__ hb,
                            const float* __restrict__ hm, const float* __restrict__ hv) {
    int n = blockIdx.x;                 // 0..1023
    bool isz = n < HH;
    int r = isz ? n : n - HH;
    float g    = isz ? zg[r] : hg[r];
    float beta = isz ? zb[r] : hb[r];
    float mean = isz ? zm[r] : hm[r];
    float var  = isz ? zv[r] : hv[r];
    float bias = isz ? bz[r] : bh[r];
    float s = g * rsqrtf(var + 1e-5f);
    const float* src = (isz ? Wz : Wh) + (long long)r * FF;
    for (int k = threadIdx.x; k < FF; k += blockDim.x)
        g_Wc[(long long)n * FF + k] = src[k] * s;
    if (threadIdx.x == 0) g_shift[n] = (bias - mean) * s + beta;
}

// ---------------- GEMM1: wzh = x @ Wc^T + shift ----------------
// M=16000 (dedup), N=1024, K=512. 128x128 tile, BK=16, 256 threads, 8x8/thread.
__global__ void __launch_bounds__(256) gemm1_kernel(const float* __restrict__ x) {
    __shared__ float As[16][132];
    __shared__ float Bs[16][132];
    const int bm = blockIdx.x, bn = blockIdx.y;
    const int tid = threadIdx.x;
    const int tx = tid & 15, ty = tid >> 4;

    const float* aptr[2]; int ak[2]; int arow[2];
    const float* bptr[2];
#pragma unroll
    for (int l = 0; l < 2; l++) {
        int idx = tid + l * 256;
        int row = idx >> 2;
        int k4  = (idx & 3) << 2;
        aptr[l] = x + (long long)(bm * 128 + row) * FF + k4;
        ak[l] = k4; arow[l] = row;
        bptr[l] = g_Wc + (long long)(bn * 128 + row) * FF + k4;
    }

    float acc[8][8] = {};
    for (int kt = 0; kt < FF; kt += 16) {
#pragma unroll
        for (int l = 0; l < 2; l++) {
            float4 v = *(const float4*)(aptr[l] + kt);
            As[ak[l] + 0][arow[l]] = v.x; As[ak[l] + 1][arow[l]] = v.y;
            As[ak[l] + 2][arow[l]] = v.z; As[ak[l] + 3][arow[l]] = v.w;
            float4 w = *(const float4*)(bptr[l] + kt);
            Bs[ak[l] + 0][arow[l]] = w.x; Bs[ak[l] + 1][arow[l]] = w.y;
            Bs[ak[l] + 2][arow[l]] = w.z; Bs[ak[l] + 3][arow[l]] = w.w;
        }
        __syncthreads();
#pragma unroll
        for (int kk = 0; kk < 16; kk++) {
            float a[8], bb[8];
            *(float4*)a       = *(const float4*)&As[kk][ty * 8];
            *(float4*)(a + 4) = *(const float4*)&As[kk][ty * 8 + 4];
            *(float4*)bb       = *(const float4*)&Bs[kk][tx * 8];
            *(float4*)(bb + 4) = *(const float4*)&Bs[kk][tx * 8 + 4];
#pragma unroll
            for (int i = 0; i < 8; i++)
#pragma unroll
                for (int j = 0; j < 8; j++) acc[i][j] += a[i] * bb[j];
        }
        __syncthreads();
    }
    int n0 = bn * 128 + tx * 8;
    float4 s0 = *(const float4*)(g_shift + n0);
    float4 s1 = *(const float4*)(g_shift + n0 + 4);
#pragma unroll
    for (int i = 0; i < 8; i++) {
        int m = bm * 128 + ty * 8 + i;
        float* cp = g_wzh + (long long)m * NOUT + n0;
        float4 o0 = {acc[i][0] + s0.x, acc[i][1] + s0.y, acc[i][2] + s0.z, acc[i][3] + s0.w};
        float4 o1 = {acc[i][4] + s1.x, acc[i][5] + s1.y, acc[i][6] + s1.z, acc[i][7] + s1.w};
        *(float4*)cp = o0; *(float4*)(cp + 4) = o1;
    }
}

// ---------------- dummy: shifts ncu capture slot onto recur_kernel ----------------
__global__ void dummy_kernel() {}

// ---------------- Recurrence: one 8-CTA cluster per batch ----------------
// Per CTA: 64 j-indices -> 128 dots (uz,uh). Thread t: dot d=t>>1, k-half=t&1.
// U split: 96 k/thread in regs, 160 k/thread in smem (float4 [40][256]).
// Cross-CTA h exchange: st.async + tx-accounting mbarriers (no cluster.sync in loop).
#define NR   8
#define JPC  64
#define KREG 96
#define KSH  160                         // 40 float4 per thread
#define USM_FLOATS (40 * 256 * 4)        // 40960 floats = 163840 B
#define SMEM_BYTES (4096 + USM_FLOATS * 4 + 16)

__global__ void __cluster_dims__(NR, 1, 1) __launch_bounds__(256, 1)
recur_kernel(const float* __restrict__ U) {
    extern __shared__ float smem[];
    float*  hbuf = smem;                            // [2][512]
    float4* Usm  = (float4*)(smem + 1024);          // [40][256]
    unsigned long long* mbar = (unsigned long long*)(smem + 1024 + USM_FLOATS);  // [2]

    const int rank = blockIdx.x;               // cluster rank 0..7
    const int b    = blockIdx.y;               // batch
    const int tid  = threadIdx.x;
    const int d    = tid >> 1;                 // dot id 0..127
    const int half = tid & 1;                  // k half
    const int jj   = d >> 1;
    const int type = d & 1;                    // 0: z-gate, 1: h-cand
    const int j    = rank * JPC + jj;
    const int grow = type ? (HH + j) : j;      // U row
    const int koff = half * 256;

    const uint32_t mbar_u32 = (uint32_t)__cvta_generic_to_shared(mbar);

    // U slice: first 96 k in registers
    float Ur[KREG];
    {
        const float4* up = (const float4*)(U + (long long)grow * HH + koff);
#pragma unroll
        for (int i = 0; i < KREG / 4; i++) {
            float4 v = up[i];
            Ur[4*i] = v.x; Ur[4*i+1] = v.y; Ur[4*i+2] = v.z; Ur[4*i+3] = v.w;
        }
        // next 160 k to smem, [i][tid] float4 layout (conflict-free)
        const float4* up2 = (const float4*)(U + (long long)grow * HH + koff + KREG);
        for (int i = 0; i < 40; i++) Usm[i * 256 + tid] = up2[i];
    }

    // h buffers = 0
    for (int i = tid; i < 1024; i += 256) hbuf[i] = 0.f;

    // init + prime both barriers (count=1; each phase needs 1 arrive + 2048 tx bytes)
    if (tid == 0) {
        asm volatile("mbarrier.init.shared.b64 [%0], 1;" :: "r"(mbar_u32) : "memory");
        asm volatile("mbarrier.init.shared.b64 [%0], 1;" :: "r"(mbar_u32 + 8) : "memory");
        asm volatile("mbarrier.arrive.expect_tx.shared.b64 _, [%0], 2048;" :: "r"(mbar_u32) : "memory");
        asm volatile("mbarrier.arrive.expect_tx.shared.b64 _, [%0], 2048;" :: "r"(mbar_u32 + 8) : "memory");
    }
    __syncthreads();
    asm volatile("barrier.cluster.arrive.aligned;" ::: "memory");
    asm volatile("barrier.cluster.wait.aligned;"   ::: "memory");

    const bool owner = (tid & 3) == 0;
    const int  jown  = tid >> 2;               // 0..63
    const int  jg    = rank * JPC + jown;      // global h index this lane updates
    float* hout = g_h + (long long)b * T2 * HH + jg;

    // wzh row for step t (dedup: second half reads mirrored batch's rows)
    auto rowp = [&](int t) -> const float* {
        int r = (t < TSEQ) ? (b * TSEQ + t) : ((BB - 1 - b) * TSEQ + (t - TSEQ));
        return g_wzh + (long long)r * NOUT + jg;
    };

    float pz = 0.f, ph = 0.f;
    if (owner) { const float* rp = rowp(0); pz = rp[0]; ph = rp[HH]; }
    float hprev = 0.f;                        // owner's own h value

    for (int t = 0; t < T2; t++) {
        // wait for this step's input buffer (all 512 values arrived via st.async tx)
        if (t >= 1) {
            uint32_t barb = mbar_u32 + (uint32_t)((t & 1) * 8);
            uint32_t p = (uint32_t)(((t - 1) >> 1) & 1);
            asm volatile(
                "{\n\t.reg .pred P;\n\t"
                "WL%=:\n\t"
                "mbarrier.try_wait.parity.acquire.cluster.shared::cta.b64 P, [%0], %1, 0x989680;\n\t"
                "@!P bra WL%=;\n\t}"
                :: "r"(barb), "r"(p) : "memory");
            // re-prime this barrier for its next fill (during step t+1, waited at t+2)
            if (tid == 0)
                asm volatile("mbarrier.arrive.expect_tx.shared.b64 _, [%0], 2048;"
                             :: "r"(barb) : "memory");
        }

        const float* hc = hbuf + (t & 1) * 512;
        float*       hn = hbuf + ((t + 1) & 1) * 512;

        // prefetch next step's wz/wh
        float pz2 = 0.f, ph2 = 0.f;
        if (owner && t + 1 < T2) { const float* rp = rowp(t + 1); pz2 = rp[0]; ph2 = rp[HH]; }

        // dot product: 4 independent accumulators
        float a0 = 0.f, a1 = 0.f, a2 = 0.f, a3 = 0.f;
        const float4* h4 = (const float4*)(hc + koff);
#pragma unroll
        for (int i = 0; i < KREG / 4; i++) {
            float4 hv = h4[i];
            a0 += Ur[4*i]   * hv.x;
            a1 += Ur[4*i+1] * hv.y;
            a2 += Ur[4*i+2] * hv.z;
            a3 += Ur[4*i+3] * hv.w;
        }
        const float4* hs = (const float4*)(hc + koff + KREG);
#pragma unroll
        for (int i = 0; i < 40; i++) {
            float4 uv = Usm[i * 256 + tid];
            float4 hv = hs[i];
            a0 += uv.x * hv.x;
            a1 += uv.y * hv.y;
            a2 += uv.z * hv.z;
            a3 += uv.w * hv.w;
        }
        float acc = (a0 + a1) + (a2 + a3);

        // reduce 2 k-halves; then exchange z<->h dot
        acc += __shfl_xor_sync(0xffffffffu, acc, 1);
        float other = __shfl_xor_sync(0xffffffffu, acc, 2);

        if (owner) {
            float uz = acc, uh = other;
            float zt = 1.f / (1.f + expf(-(pz + uz)));
            float hcand = fmaxf(ph + uh, 0.f);
            float hnew = zt * hprev + (1.f - zt) * hcand;
            hprev = hnew;
            hout[(long long)t * HH] = hnew;
            if (t + 1 < T2) {
                uint32_t lslot = (uint32_t)__cvta_generic_to_shared(hn + jg);
                uint32_t lbar  = mbar_u32 + (uint32_t)(((t + 1) & 1) * 8);
                uint32_t vv = __float_as_uint(hnew);
#pragma unroll
                for (int rr = 0; rr < NR; rr++) {
                    uint32_t ra, rb;
                    asm("mapa.shared::cluster.u32 %0, %1, %2;" : "=r"(ra) : "r"(lslot), "r"(rr));
                    asm("mapa.shared::cluster.u32 %0, %1, %2;" : "=r"(rb) : "r"(lbar), "r"(rr));
                    asm volatile(
                        "st.async.shared::cluster.mbarrier::complete_tx::bytes.b32 [%0], %1, [%2];"
                        :: "r"(ra), "r"(vv), "r"(rb) : "memory");
                }
            }
        }
        pz = pz2; ph = ph2;
    }

    // keep cluster resident until all CTAs done (smem lifetime for late st.async)
    asm volatile("barrier.cluster.arrive.aligned;" ::: "memory");
    asm volatile("barrier.cluster.wait.aligned;"   ::: "memory");
}

// ---------------- LayerNorm over concat(h_f, h_b_rev) ----------------
__global__ void __launch_bounds__(256) ln_kernel(const float* __restrict__ lng,
                                                 const float* __restrict__ lnb) {
    int m = blockIdx.x;                 // 0..15999
    int b = m / TSEQ, t = m - b * TSEQ;
    int tid = threadIdx.x;
    int d0 = tid * 4;
    const float* src = (d0 < HH)
        ? (g_h + (long long)(b * T2 + t) * HH + d0)
        : (g_h + (long long)((BB - 1 - b) * T2 + TSEQ + t) * HH + (d0 - HH));
    float4 v = *(const float4*)src;
    float s = v.x + v.y + v.z + v.w;
    float q = v.x*v.x + v.y*v.y + v.z*v.z + v.w*v.w;
#pragma unroll
    for (int o = 16; o; o >>= 1) {
        s += __shfl_xor_sync(0xffffffffu, s, o);
        q += __shfl_xor_sync(0xffffffffu, q, o);
    }
    __shared__ float ss[8], qq[8];
    __shared__ float mu_s, rs_s;
    if ((tid & 31) == 0) { ss[tid >> 5] = s; qq[tid >> 5] = q; }
    __syncthreads();
    if (tid == 0) {
        float S = 0.f, Q = 0.f;
#pragma unroll
        for (int i = 0; i < 8; i++) { S += ss[i]; Q += qq[i]; }
        float mu = S * (1.f / NOUT);
        float var = Q * (1.f / NOUT) - mu * mu;
        mu_s = mu; rs_s = rsqrtf(var + 1e-5f);
    }
    __syncthreads();
    float mu = mu_s, rs = rs_s;
    float4 g4 = *(const float4*)(lng + d0);
    float4 b4 = *(const float4*)(lnb + d0);
    float4 o;
    o.x = (v.x - mu) * rs * g4.x + b4.x;
    o.y = (v.y - mu) * rs * g4.y + b4.y;
    o.z = (v.z - mu) * rs * g4.z + b4.z;
    o.w = (v.w - mu) * rs * g4.w + b4.w;
    *(float4*)(g_A2 + (long long)m * NOUT + d0) = o;
}

// ---------------- GEMM2: tanh(A2 @ pj_W^T + pj_b) -> d_out ----------------
__global__ void __launch_bounds__(256) gemm2_kernel(const float* __restrict__ pjW,
                                                    const float* __restrict__ pjb,
                                                    float* __restrict__ out) {
    __shared__ float As[16][132];
    __shared__ float Bs[16][132];
    const int bm = blockIdx.x, bn = blockIdx.y;
    const int tid = threadIdx.x;
    const int tx = tid & 15, ty = tid >> 4;

    const float* aptr[2]; int ak[2]; int arow[2];
    const float* bptr[2];
#pragma unroll
    for (int l = 0; l < 2; l++) {
        int idx = tid + l * 256;
        int row = idx >> 2;
        int k4  = (idx & 3) << 2;
        aptr[l] = g_A2 + (long long)(bm * 128 + row) * NOUT + k4;
        ak[l] = k4; arow[l] = row;
        bptr[l] = pjW + (long long)(bn * 128 + row) * NOUT + k4;
    }

    float acc[8][8] = {};
    for (int kt = 0; kt < NOUT; kt += 16) {
#pragma unroll
        for (int l = 0; l < 2; l++) {
            float4 v = *(const float4*)(aptr[l] + kt);
            As[ak[l] + 0][arow[l]] = v.x; As[ak[l] + 1][arow[l]] = v.y;
            As[ak[l] + 2][arow[l]] = v.z; As[ak[l] + 3][arow[l]] = v.w;
            float4 w = *(const float4*)(bptr[l] + kt);
            Bs[ak[l] + 0][arow[l]] = w.x; Bs[ak[l] + 1][arow[l]] = w.y;
            Bs[ak[l] + 2][arow[l]] = w.z; Bs[ak[l] + 3][arow[l]] = w.w;
        }
        __syncthreads();
#pragma unroll
        for (int kk = 0; kk < 16; kk++) {
            float a[8], bb[8];
            *(float4*)a       = *(const float4*)&As[kk][ty * 8];
            *(float4*)(a + 4) = *(const float4*)&As[kk][ty * 8 + 4];
            *(float4*)bb       = *(const float4*)&Bs[kk][tx * 8];
            *(float4*)(bb + 4) = *(const float4*)&Bs[kk][tx * 8 + 4];
#pragma unroll
            for (int i = 0; i < 8; i++)
#pragma unroll
                for (int j = 0; j < 8; j++) acc[i][j] += a[i] * bb[j];
        }
        __syncthreads();
    }
    int n0 = bn * 128 + tx * 8;
    float4 s0 = *(const float4*)(pjb + n0);
    float4 s1 = *(const float4*)(pjb + n0 + 4);
#pragma unroll
    for (int i = 0; i < 8; i++) {
        int m = bm * 128 + ty * 8 + i;
        float* cp = out + (long long)m * NOUT + n0;
        float4 o0 = {tanhf(acc[i][0] + s0.x), tanhf(acc[i][1] + s0.y),
                     tanhf(acc[i][2] + s0.z), tanhf(acc[i][3] + s0.w)};
        float4 o1 = {tanhf(acc[i][4] + s1.x), tanhf(acc[i][5] + s1.y),
                     tanhf(acc[i][6] + s1.z), tanhf(acc[i][7] + s1.w)};
        *(float4*)cp = o0; *(float4*)(cp + 4) = o1;
    }
}

// ---------------- tail: x_len passthrough (value-cast to float) ----------------
__global__ void tail_kernel(const int* __restrict__ xlen, float* __restrict__ out, int extra) {
    int i = threadIdx.x;
    if (i < 16 && i < extra) out[(long long)BB * TSEQ * NOUT + i] = (float)xlen[i];
}

// ---------------- launch ----------------
extern "C" void kernel_launch(void* const* d_in, const int* in_sizes, int n_in,
                              void* d_out, int out_size) {
    const float* x   = (const float*)d_in[0];
    const int*  xlen = (const int*)  d_in[1];
    const float* Wz  = (const float*)d_in[2];
    const float* bz  = (const float*)d_in[3];
    const float* Wh  = (const float*)d_in[4];
    const float* bh  = (const float*)d_in[5];
    const float* U   = (const float*)d_in[6];
    const float* zg  = (const float*)d_in[7];
    const float* zb  = (const float*)d_in[8];
    const float* zm  = (const float*)d_in[9];
    const float* zv  = (const float*)d_in[10];
    const float* hg  = (const float*)d_in[11];
    const float* hb  = (const float*)d_in[12];
    const float* hm  = (const float*)d_in[13];
    const float* hv  = (const float*)d_in[14];
    const float* lng = (const float*)d_in[15];
    const float* lnb = (const float*)d_in[16];
    const float* pjW = (const float*)d_in[17];
    const float* pjb = (const float*)d_in[18];
    float* out = (float*)d_out;

    prep_kernel<<<NOUT, 128>>>(Wz, bz, Wh, bh, zg, zb, zm, zv, hg, hb, hm, hv);
    gemm1_kernel<<<dim3(125, 8), 256>>>(x);    // M=16000 (dedup)

    dummy_kernel<<<1, 32>>>();                 // keep ncu capture slot on recur

    cudaFuncSetAttribute(recur_kernel, cudaFuncAttributeMaxDynamicSharedMemorySize, SMEM_BYTES);
    recur_kernel<<<dim3(NR, BB), 256, SMEM_BYTES>>>(U);

    ln_kernel<<<BB * TSEQ, 256>>>(lng, lnb);
    gemm2_kernel<<<dim3(125, 8), 256>>>(pjW, pjb, out);

    long long total = (long long)BB * TSEQ * NOUT;
    if ((long long)out_size > total)
        tail_kernel<<<1, 32>>>(xlen, out, (int)((long long)out_size - total));
}